// round 15
// baseline (speedup 1.0000x reference)
#include <cuda_runtime.h>
#include <cuda_fp16.h>
#include <cstdint>

#define BT_   8192
#define C_    1024
#define S_    4096
#define QH_   4
#define EPS_  1e-5f
#define NSPLIT 4
#define SSEG  1024            // S per split

// ---------------- scratch ----------------
__device__ __half g_q[(size_t)BT_ * 1024];   // 16MB [row][h*256 + d]
__device__ __half g_k[(size_t)S_ * 256];     //  2MB [s][d]
__device__ __half g_vt[256ull * S_];         //  2MB [d][s]
__device__ float g_part[(size_t)NSPLIT * BT_ * C_]; // 134MB partial outputs

// ---------------- helpers ----------------
__device__ __forceinline__ uint32_t smem_u32(const void* p) {
    uint32_t a;
    asm("{ .reg .u64 t; cvta.to.shared.u64 t, %1; cvt.u32.u64 %0, t; }" : "=r"(a) : "l"(p));
    return a;
}
#define CPA16(saddr, gptr) \
    asm volatile("cp.async.cg.shared.global [%0], [%1], 16;" :: "r"(saddr), "l"(gptr))
#define CPCOMMIT() asm volatile("cp.async.commit_group;" ::: "memory")
#define CPWAIT(n)  asm volatile("cp.async.wait_group " #n ";" ::: "memory")

__device__ __forceinline__ void ldsm4(uint32_t* r, uint32_t addr) {
    asm volatile("ldmatrix.sync.aligned.m8n8.x4.shared.b16 {%0,%1,%2,%3}, [%4];"
                 : "=r"(r[0]), "=r"(r[1]), "=r"(r[2]), "=r"(r[3]) : "r"(addr));
}
__device__ __forceinline__ void mma16816(float* c, const uint32_t* a, const uint32_t* b) {
    asm volatile("mma.sync.aligned.m16n8k16.row.col.f32.f16.f16.f32 "
                 "{%0,%1,%2,%3}, {%4,%5,%6,%7}, {%8,%9}, {%0,%1,%2,%3};"
                 : "+f"(c[0]), "+f"(c[1]), "+f"(c[2]), "+f"(c[3])
                 : "r"(a[0]), "r"(a[1]), "r"(a[2]), "r"(a[3]), "r"(b[0]), "r"(b[1]));
}
__device__ __forceinline__ uint32_t pack_h2(float f0, float f1) {
    __half2 h = __floats2half2_rn(f0, f1);
    return *reinterpret_cast<uint32_t*>(&h);
}

// ---------------------------------------------------------------------------
// LayerNorm -> g_q (fp16)
// ---------------------------------------------------------------------------
__global__ void __launch_bounds__(256) ln_kernel(const float* __restrict__ res,
                                                 const float* __restrict__ gam,
                                                 const float* __restrict__ bet) {
    const int row = blockIdx.x;
    const float* x = res + (size_t)row * C_;
    const int t = threadIdx.x;

    float v[4];
    float s = 0.f;
#pragma unroll
    for (int i = 0; i < 4; i++) { v[i] = x[t + 256 * i]; s += v[i]; }

    __shared__ float red[8];
    __shared__ float sh_mu, sh_rs;
#pragma unroll
    for (int o = 16; o; o >>= 1) s += __shfl_xor_sync(0xffffffffu, s, o);
    if ((t & 31) == 0) red[t >> 5] = s;
    __syncthreads();
    if (t == 0) {
        float tot = 0.f;
#pragma unroll
        for (int i = 0; i < 8; i++) tot += red[i];
        sh_mu = tot * (1.0f / (float)C_);
    }
    __syncthreads();
    const float mu = sh_mu;
    float s2 = 0.f;
#pragma unroll
    for (int i = 0; i < 4; i++) { float d = v[i] - mu; s2 += d * d; }
#pragma unroll
    for (int o = 16; o; o >>= 1) s2 += __shfl_xor_sync(0xffffffffu, s2, o);
    if ((t & 31) == 0) red[t >> 5] = s2;
    __syncthreads();
    if (t == 0) {
        float tot = 0.f;
#pragma unroll
        for (int i = 0; i < 8; i++) tot += red[i];
        sh_rs = rsqrtf(tot * (1.0f / (float)C_) + EPS_);
    }
    __syncthreads();
    const float rs = sh_rs;

#pragma unroll
    for (int i = 0; i < 4; i++) {
        int c = t + 256 * i;
        float y = (v[i] - mu) * rs * gam[c] + bet[c];
        g_q[(size_t)row * 1024 + c] = __float2half(y);
    }
}

__global__ void __launch_bounds__(256) kext_kernel(const float* __restrict__ wfc) {
    int idx = blockIdx.x * 256 + threadIdx.x;
    g_k[idx] = __float2half(wfc[idx]);
}

__global__ void __launch_bounds__(256) vext_kernel(const float* __restrict__ wproj) {
    int idx = blockIdx.x * 256 + threadIdx.x;
    float v = wproj[idx];
    int r = idx >> 10, cc = idx & 1023;
    int d = r & 255;
    int s = cc * 4 + (r >> 8);
    g_vt[(size_t)d * 4096 + s] = __float2half(v);
}

// ---------------------------------------------------------------------------
// Reduce: out = residual + sum of 4 partials
// ---------------------------------------------------------------------------
__global__ void __launch_bounds__(256) reduce_kernel(const float* __restrict__ res,
                                                     float* __restrict__ out) {
    const size_t i = ((size_t)blockIdx.x * 256 + threadIdx.x) * 4;
    float4 a = *(const float4*)(res + i);
    float4 p0 = *(const float4*)(g_part + i);
    float4 p1 = *(const float4*)(g_part + (size_t)BT_ * C_ + i);
    float4 p2 = *(const float4*)(g_part + 2ull * BT_ * C_ + i);
    float4 p3 = *(const float4*)(g_part + 3ull * BT_ * C_ + i);
    float4 o;
    o.x = a.x + (p0.x + p1.x) + (p2.x + p3.x);
    o.y = a.y + (p0.y + p1.y) + (p2.y + p3.y);
    o.z = a.z + (p0.z + p1.z) + (p2.z + p3.z);
    o.w = a.w + (p0.w + p1.w) + (p2.w + p3.w);
    *(float4*)(out + i) = o;
}

// ---------------------------------------------------------------------------
// Fused kernel: CTA = 128 rows x 1 head x 1 S-split(1024); S chunks of 64.
// Register-resident P: each warp owns 16 rows end-to-end. 1 barrier/chunk.
// GEMM1 warp tile 16m x 64s; GEMM2 warp tile 16m x 256d (A = P in registers).
// SMEM: Q[128][528B], K 2x[64][528B], V 2x[256][144B] = 208896B. No P buffer.
// ---------------------------------------------------------------------------
#define SQ_OFF   0            // 128*528     = 67584
#define SK_OFF   67584        // 2 x 64*528  = 67584
#define SK_SZ    33792
#define SV_OFF   135168       // 2 x 256*144 = 73728
#define SV_SZ    36864
#define SMEM_TOT 208896
#define NIT      (SSEG / 64)  // 16 chunks per split

__global__ void __launch_bounds__(256, 1) fused_kernel() {
    extern __shared__ char smem[];
    const uint32_t sb = smem_u32(smem);

    const int t = threadIdx.x;
    const int lane = t & 31;
    const int wid = t >> 5;
    const int r = lane >> 2;        // 0..7
    const int u = lane & 3;         // 0..3
    const int head = blockIdx.y;
    const int row0 = blockIdx.x * 128;
    const int sBase = blockIdx.z * SSEG;
    const int m0 = wid * 16;        // warp owns rows m0..m0+15 for BOTH GEMMs

    // ---- prologue: issue Q + K(0) + V(0) as one group ----
#pragma unroll
    for (int i = 0; i < 16; i++) {
        int idx = i * 256 + t;
        int m = idx >> 5, c = idx & 31;
        CPA16(sb + SQ_OFF + m * 528 + c * 16,
              (const void*)(g_q + (size_t)(row0 + m) * 1024 + head * 256 + c * 8));
    }
#pragma unroll
    for (int i = 0; i < 8; i++) {
        int idx = i * 256 + t;
        int s = idx >> 5, c = idx & 31;
        CPA16(sb + SK_OFF + s * 528 + c * 16,
              (const void*)(g_k + (size_t)(sBase + s) * 256 + c * 8));
    }
#pragma unroll
    for (int i = 0; i < 8; i++) {
        int idx = i * 256 + t;
        int d = idx >> 3, c = idx & 7;
        CPA16(sb + SV_OFF + d * 144 + c * 16,
              (const void*)(g_vt + (size_t)d * 4096 + sBase + c * 8));
    }
    CPCOMMIT();
    CPWAIT(0);
    __syncthreads();

    // ldmatrix lane addressing
    const uint32_t qa = sb + SQ_OFF + (uint32_t)((m0 + (lane & 15)) * 528 + (lane >> 4) * 16);
    const int brow = (lane & 7) + ((lane >> 4) << 3);
    const int bc8  = ((lane >> 3) & 1) << 3;
    const uint32_t kb0 = sb + SK_OFF + (uint32_t)(brow * 528 + bc8 * 2);
    const uint32_t vb0 = sb + SV_OFF + (uint32_t)(brow * 144 + bc8 * 2);

    // O accumulators: 32 d-tiles (8 wide), 4 f32 each  (rows m0+r / m0+r+8)
    float c2[32][4];
#pragma unroll
    for (int i = 0; i < 32; i++)
#pragma unroll
        for (int j = 0; j < 4; j++) c2[i][j] = 0.f;

    for (int it = 0; it < NIT; it++) {
        const int buf = it & 1;
        const uint32_t kb = kb0 + buf * SK_SZ;
        const uint32_t vb = vb0 + buf * SV_SZ;

        // issue K(it+1) + V(it+1) into the other buffers (fly under both GEMMs)
        if (it < NIT - 1) {
            const int sn = sBase + (it + 1) * 64;
            const uint32_t ko = sb + SK_OFF + (buf ^ 1) * SK_SZ;
            const uint32_t vo = sb + SV_OFF + (buf ^ 1) * SV_SZ;
#pragma unroll
            for (int i = 0; i < 8; i++) {
                int idx = i * 256 + t;
                int s = idx >> 5, c = idx & 31;
                CPA16(ko + s * 528 + c * 16,
                      (const void*)(g_k + (size_t)(sn + s) * 256 + c * 8));
            }
#pragma unroll
            for (int i = 0; i < 8; i++) {
                int idx = i * 256 + t;
                int d = idx >> 3, c = idx & 7;
                CPA16(vo + d * 144 + c * 16,
                      (const void*)(g_vt + (size_t)d * 4096 + sn + c * 8));
            }
            CPCOMMIT();
        }

        // ---- GEMM1: scores[16 x 64] per warp ----
        float c1[8][4];
#pragma unroll
        for (int i = 0; i < 8; i++)
#pragma unroll
            for (int j = 0; j < 4; j++) c1[i][j] = 0.f;

#pragma unroll 8
        for (int ks = 0; ks < 16; ks++) {
            uint32_t a[4];
            ldsm4(a, qa + ks * 32);
#pragma unroll
            for (int st = 0; st < 4; st++) {
                uint32_t b[4];
                ldsm4(b, kb + (uint32_t)(st * (16 * 528) + ks * 32));
                mma16816(c1[st * 2],     a, b);
                mma16816(c1[st * 2 + 1], a, b + 2);
            }
        }

        // ---- relu^2 -> GEMM2 A-fragments (registers, warp-local) ----
        uint32_t aP[4][4];
#pragma unroll
        for (int j = 0; j < 4; j++) {          // k-step j covers score tiles 2j,2j+1
#pragma unroll
            for (int h = 0; h < 4; h++) {
                const int nt = 2 * j + (h >> 1);
                const int base = (h & 1) * 2;  // 0 -> row r; 1 -> row r+8
                float p0 = fmaxf(c1[nt][base], 0.f);
                float p1 = fmaxf(c1[nt][base + 1], 0.f);
                aP[j][h] = pack_h2(p0 * p0, p1 * p1);
            }
        }

        // ---- GEMM2: O[16 x 256] += P . V^T  (no barrier needed) ----
#pragma unroll
        for (int j = 0; j < 4; j++) {
#pragma unroll
            for (int dt = 0; dt < 16; dt++) {
                uint32_t vh[4];
                ldsm4(vh, vb + (uint32_t)(dt * (16 * 144) + j * 32));
                mma16816(c2[dt * 2],     aP[j], vh);
                mma16816(c2[dt * 2 + 1], aP[j], vh + 2);
            }
        }

        CPWAIT(0);              // K(it+1)+V(it+1) landed
        __syncthreads();        // single barrier: buffer flip visibility
    }

    // ---- epilogue: write partial O (no residual) ----
    float* po = g_part + (size_t)blockIdx.z * BT_ * C_;
    {
        const int rowA = row0 + m0 + r;
        const int rowB = rowA + 8;
        float* oA = po + (size_t)rowA * C_ + head * 256;
        float* oB = po + (size_t)rowB * C_ + head * 256;
#pragma unroll
        for (int nt = 0; nt < 32; nt++) {
            const int col = nt * 8 + 2 * u;
            *(float2*)(oA + col) = make_float2(c2[nt][0], c2[nt][1]);
            *(float2*)(oB + col) = make_float2(c2[nt][2], c2[nt][3]);
        }
    }
}

// ---------------------------------------------------------------------------
extern "C" void kernel_launch(void* const* d_in, const int* in_sizes, int n_in,
                              void* d_out, int out_size) {
    (void)in_sizes; (void)n_in; (void)out_size;
    const float* residual = (const float*)d_in[0];
    const float* w_fc     = (const float*)d_in[1];
    const float* w_proj   = (const float*)d_in[2];
    const float* ln_g     = (const float*)d_in[3];
    const float* ln_b     = (const float*)d_in[4];
    float* out = (float*)d_out;

    cudaFuncSetAttribute(fused_kernel, cudaFuncAttributeMaxDynamicSharedMemorySize,
                         SMEM_TOT);

    ln_kernel<<<BT_, 256>>>(residual, ln_g, ln_b);
    kext_kernel<<<4096, 256>>>(w_fc);
    vext_kernel<<<4096, 256>>>(w_proj);
    fused_kernel<<<dim3(64, QH_, NSPLIT), 256, SMEM_TOT>>>();
    reduce_kernel<<<BT_ * C_ / 1024, 256>>>(residual, out);
}

// round 16
// speedup vs baseline: 1.0620x; 1.0620x over previous
#include <cuda_runtime.h>
#include <cuda_fp16.h>
#include <cstdint>

#define BT_   8192
#define C_    1024
#define S_    4096
#define QH_   4
#define EPS_  1e-5f
#define NSPLIT 4
#define SSEG  1024            // S per split

// ---------------- scratch ----------------
__device__ __half g_q[(size_t)BT_ * 1024];   // 16MB [row][h*256 + d]
__device__ __half g_k[(size_t)S_ * 256];     //  2MB [s][d]
__device__ __half g_vt[256ull * S_];         //  2MB [d][s]
__device__ __half g_part[(size_t)NSPLIT * BT_ * C_]; // 67MB fp16 partials

// ---------------- helpers ----------------
__device__ __forceinline__ uint32_t smem_u32(const void* p) {
    uint32_t a;
    asm("{ .reg .u64 t; cvta.to.shared.u64 t, %1; cvt.u32.u64 %0, t; }" : "=r"(a) : "l"(p));
    return a;
}
#define CPA16(saddr, gptr) \
    asm volatile("cp.async.cg.shared.global [%0], [%1], 16;" :: "r"(saddr), "l"(gptr))
#define CPCOMMIT() asm volatile("cp.async.commit_group;" ::: "memory")
#define CPWAIT(n)  asm volatile("cp.async.wait_group " #n ";" ::: "memory")

__device__ __forceinline__ void ldsm4(uint32_t* r, uint32_t addr) {
    asm volatile("ldmatrix.sync.aligned.m8n8.x4.shared.b16 {%0,%1,%2,%3}, [%4];"
                 : "=r"(r[0]), "=r"(r[1]), "=r"(r[2]), "=r"(r[3]) : "r"(addr));
}
__device__ __forceinline__ void mma16816(float* c, const uint32_t* a, const uint32_t* b) {
    asm volatile("mma.sync.aligned.m16n8k16.row.col.f32.f16.f16.f32 "
                 "{%0,%1,%2,%3}, {%4,%5,%6,%7}, {%8,%9}, {%0,%1,%2,%3};"
                 : "+f"(c[0]), "+f"(c[1]), "+f"(c[2]), "+f"(c[3])
                 : "r"(a[0]), "r"(a[1]), "r"(a[2]), "r"(a[3]), "r"(b[0]), "r"(b[1]));
}
__device__ __forceinline__ uint32_t pack_h2(float f0, float f1) {
    __half2 h = __floats2half2_rn(f0, f1);
    return *reinterpret_cast<uint32_t*>(&h);
}

// ---------------------------------------------------------------------------
// LayerNorm -> g_q (fp16), single-pass mean/var
// ---------------------------------------------------------------------------
__global__ void __launch_bounds__(256) ln_kernel(const float* __restrict__ res,
                                                 const float* __restrict__ gam,
                                                 const float* __restrict__ bet) {
    const int row = blockIdx.x;
    const float* x = res + (size_t)row * C_;
    const int t = threadIdx.x;

    float v[4];
    float s = 0.f, q = 0.f;
#pragma unroll
    for (int i = 0; i < 4; i++) {
        v[i] = x[t + 256 * i];
        s += v[i];
        q += v[i] * v[i];
    }

    __shared__ float red_s[8], red_q[8];
    __shared__ float sh_mu, sh_rs;
#pragma unroll
    for (int o = 16; o; o >>= 1) {
        s += __shfl_xor_sync(0xffffffffu, s, o);
        q += __shfl_xor_sync(0xffffffffu, q, o);
    }
    if ((t & 31) == 0) { red_s[t >> 5] = s; red_q[t >> 5] = q; }
    __syncthreads();
    if (t == 0) {
        float ts = 0.f, tq = 0.f;
#pragma unroll
        for (int i = 0; i < 8; i++) { ts += red_s[i]; tq += red_q[i]; }
        float mu = ts * (1.0f / (float)C_);
        float var = tq * (1.0f / (float)C_) - mu * mu;
        sh_mu = mu;
        sh_rs = rsqrtf(var + EPS_);
    }
    __syncthreads();
    const float mu = sh_mu;
    const float rs = sh_rs;

#pragma unroll
    for (int i = 0; i < 4; i++) {
        int c = t + 256 * i;
        float y = (v[i] - mu) * rs * gam[c] + bet[c];
        g_q[(size_t)row * 1024 + c] = __float2half(y);
    }
}

// K + V^T extraction in one kernel
__global__ void __launch_bounds__(256) kvext_kernel(const float* __restrict__ wfc,
                                                    const float* __restrict__ wproj) {
    int idx = blockIdx.x * 256 + threadIdx.x;
    // K: [s][d] direct
    g_k[idx] = __float2half(wfc[idx]);
    // V^T: coalesced read of wproj, scattered write
    float v = wproj[idx];
    int r = idx >> 10, cc = idx & 1023;
    int d = r & 255;
    int s = cc * 4 + (r >> 8);
    g_vt[(size_t)d * 4096 + s] = __float2half(v);
}

// ---------------------------------------------------------------------------
// Reduce: out = residual + sum of 4 fp16 partials
// ---------------------------------------------------------------------------
__global__ void __launch_bounds__(256) reduce_kernel(const float* __restrict__ res,
                                                     float* __restrict__ out) {
    const size_t i = ((size_t)blockIdx.x * 256 + threadIdx.x) * 4;
    float4 acc = *(const float4*)(res + i);
#pragma unroll
    for (int sp = 0; sp < NSPLIT; sp++) {
        uint2 raw = *(const uint2*)(g_part + (size_t)sp * BT_ * C_ + i);
        __half2 h0 = *reinterpret_cast<__half2*>(&raw.x);
        __half2 h1 = *reinterpret_cast<__half2*>(&raw.y);
        float2 f0 = __half22float2(h0);
        float2 f1 = __half22float2(h1);
        acc.x += f0.x; acc.y += f0.y; acc.z += f1.x; acc.w += f1.y;
    }
    *(float4*)(out + i) = acc;
}

// ---------------------------------------------------------------------------
// Fused kernel (identical to the 451us best): CTA = 128 rows x head x split;
// S chunks of 64; pure fp16; K,V double-buffered; 2 barriers/chunk.
// GEMM1 warp tile 32m x 32s (4x2). GEMM2 warp tile 64m x 64d (2x4).
// SMEM: Q[128][528B], P[128][144B], K 2x[64][528B], V 2x[256][144B] = 227328B.
// ---------------------------------------------------------------------------
#define SQ_OFF   0            // 128*528    = 67584
#define SP_OFF   67584        // 128*144    = 18432
#define SK_OFF   86016        // 2 x 64*528  = 67584
#define SK_SZ    33792
#define SV_OFF   153600       // 2 x 256*144 = 73728
#define SV_SZ    36864
#define SMEM_TOT 227328
#define NIT      (SSEG / 64)  // 16 chunks per split

__global__ void __launch_bounds__(256, 1) fused_kernel() {
    extern __shared__ char smem[];
    const uint32_t sb = smem_u32(smem);

    const int t = threadIdx.x;
    const int lane = t & 31;
    const int wid = t >> 5;
    const int r = lane >> 2;        // 0..7
    const int u = lane & 3;         // 0..3
    const int head = blockIdx.y;
    const int row0 = blockIdx.x * 128;
    const int sBase = blockIdx.z * SSEG;

    // GEMM1 warp coords: 4 m-groups x 2 s-halves(32 each)
    const int my = wid & 3;
    const int sx = wid >> 2;
    // GEMM2 warp coords: 2 m-halves x 4 d-quarters
    const int mh = wid & 1;
    const int dq = wid >> 1;

    // ---- prologue: issue Q + K(0) + V(0) as one group ----
#pragma unroll
    for (int i = 0; i < 16; i++) {
        int idx = i * 256 + t;
        int m = idx >> 5, c = idx & 31;
        CPA16(sb + SQ_OFF + m * 528 + c * 16,
              (const void*)(g_q + (size_t)(row0 + m) * 1024 + head * 256 + c * 8));
    }
#pragma unroll
    for (int i = 0; i < 8; i++) {
        int idx = i * 256 + t;
        int s = idx >> 5, c = idx & 31;
        CPA16(sb + SK_OFF + s * 528 + c * 16,
              (const void*)(g_k + (size_t)(sBase + s) * 256 + c * 8));
    }
#pragma unroll
    for (int i = 0; i < 8; i++) {
        int idx = i * 256 + t;
        int d = idx >> 3, c = idx & 7;
        CPA16(sb + SV_OFF + d * 144 + c * 16,
              (const void*)(g_vt + (size_t)d * 4096 + sBase + c * 8));
    }
    CPCOMMIT();
    CPWAIT(0);
    __syncthreads();

    // ldmatrix lane addressing
    const uint32_t qa = sb + SQ_OFF + (uint32_t)((my * 32 + (lane & 15)) * 528 + (lane >> 4) * 16);
    const int brow = (lane & 7) + ((lane >> 4) << 3);
    const int bc8  = ((lane >> 3) & 1) << 3;
    const uint32_t kb0 = sb + SK_OFF + (uint32_t)((sx * 32 + brow) * 528 + bc8 * 2);
    const uint32_t pa = sb + SP_OFF + (uint32_t)((mh * 64 + (lane & 15)) * 144 + (lane >> 4) * 16);
    const uint32_t vb0 = sb + SV_OFF + (uint32_t)((dq * 64 + brow) * 144 + bc8 * 2);
    const uint32_t pw = sb + SP_OFF + (uint32_t)((my * 32 + r) * 144 + (sx * 32 + 2 * u) * 2);

    float c2[4][8][4];
#pragma unroll
    for (int a = 0; a < 4; a++)
#pragma unroll
        for (int b = 0; b < 8; b++)
#pragma unroll
            for (int e = 0; e < 4; e++) c2[a][b][e] = 0.f;

    for (int it = 0; it < NIT; it++) {
        const int buf = it & 1;
        const uint32_t kb = kb0 + buf * SK_SZ;
        const uint32_t vb = vb0 + buf * SV_SZ;

        // issue K(it+1) + V(it+1) into the other buffers (fly under both GEMMs)
        if (it < NIT - 1) {
            const int sn = sBase + (it + 1) * 64;
            const uint32_t ko = sb + SK_OFF + (buf ^ 1) * SK_SZ;
            const uint32_t vo = sb + SV_OFF + (buf ^ 1) * SV_SZ;
#pragma unroll
            for (int i = 0; i < 8; i++) {
                int idx = i * 256 + t;
                int s = idx >> 5, c = idx & 31;
                CPA16(ko + s * 528 + c * 16,
                      (const void*)(g_k + (size_t)(sn + s) * 256 + c * 8));
            }
#pragma unroll
            for (int i = 0; i < 8; i++) {
                int idx = i * 256 + t;
                int d = idx >> 3, c = idx & 7;
                CPA16(vo + d * 144 + c * 16,
                      (const void*)(g_vt + (size_t)d * 4096 + sn + c * 8));
            }
            CPCOMMIT();
        }

        // ---- GEMM1: scores[128 x 64] ----
        float c1[2][4][4];
#pragma unroll
        for (int a = 0; a < 2; a++)
#pragma unroll
            for (int b = 0; b < 4; b++)
#pragma unroll
                for (int e = 0; e < 4; e++) c1[a][b][e] = 0.f;

#pragma unroll 8
        for (int ks = 0; ks < 16; ks++) {
            uint32_t a0[4], a1[4], b0[4], b1[4];
            ldsm4(a0, qa + ks * 32);
            ldsm4(a1, qa + 16 * 528 + ks * 32);
            ldsm4(b0, kb + ks * 32);
            ldsm4(b1, kb + 16 * 528 + ks * 32);
            mma16816(c1[0][0], a0, b0);  mma16816(c1[0][1], a0, b0 + 2);
            mma16816(c1[0][2], a0, b1);  mma16816(c1[0][3], a0, b1 + 2);
            mma16816(c1[1][0], a1, b0);  mma16816(c1[1][1], a1, b0 + 2);
            mma16816(c1[1][2], a1, b1);  mma16816(c1[1][3], a1, b1 + 2);
        }

        // ---- relu^2 -> P (fp16) smem ----
#pragma unroll
        for (int mt = 0; mt < 2; mt++) {
#pragma unroll
            for (int nt = 0; nt < 4; nt++) {
                uint32_t base = pw + (uint32_t)(mt * 16 * 144 + nt * 16);
#pragma unroll
                for (int half = 0; half < 2; half++) {
                    float p0 = fmaxf(c1[mt][nt][half * 2], 0.f);
                    float p1 = fmaxf(c1[mt][nt][half * 2 + 1], 0.f);
                    uint32_t a = base + half * (8 * 144);
                    *(uint32_t*)(smem + (a - sb)) = pack_h2(p0 * p0, p1 * p1);
                }
            }
        }
        __syncthreads();        // sync_mid: P visible to all warps

        // ---- GEMM2: O[128 x 256] += P . V^T ----
#pragma unroll
        for (int ks = 0; ks < 4; ks++) {
            uint32_t Ph[4][4];
#pragma unroll
            for (int mt = 0; mt < 4; mt++)
                ldsm4(Ph[mt], pa + (uint32_t)(mt * 16 * 144 + ks * 32));
#pragma unroll
            for (int h = 0; h < 4; h++) {
                uint32_t vh[4];
                ldsm4(vh, vb + (uint32_t)(h * 16 * 144 + ks * 32));
#pragma unroll
                for (int mt = 0; mt < 4; mt++) {
                    mma16816(c2[mt][2 * h],     Ph[mt], vh);
                    mma16816(c2[mt][2 * h + 1], Ph[mt], vh + 2);
                }
            }
        }

        if (it < NIT - 1) CPWAIT(0);   // K(it+1)+V(it+1) landed
        __syncthreads();               // sync_end: P free; next buffers visible
    }

    // ---- epilogue: write partial O as fp16 (no residual) ----
    __half* po = g_part + (size_t)blockIdx.z * BT_ * C_;
#pragma unroll
    for (int mt = 0; mt < 4; mt++) {
        const int rowA = row0 + mh * 64 + mt * 16 + r;
        const int rowB = rowA + 8;
        __half* oA = po + (size_t)rowA * C_ + head * 256;
        __half* oB = po + (size_t)rowB * C_ + head * 256;
#pragma unroll
        for (int j = 0; j < 8; j++) {
            const int col = dq * 64 + (j >> 1) * 16 + (j & 1) * 8 + 2 * u;
            *(uint32_t*)(oA + col) = pack_h2(c2[mt][j][0], c2[mt][j][1]);
            *(uint32_t*)(oB + col) = pack_h2(c2[mt][j][2], c2[mt][j][3]);
        }
    }
}

// ---------------------------------------------------------------------------
extern "C" void kernel_launch(void* const* d_in, const int* in_sizes, int n_in,
                              void* d_out, int out_size) {
    (void)in_sizes; (void)n_in; (void)out_size;
    const float* residual = (const float*)d_in[0];
    const float* w_fc     = (const float*)d_in[1];
    const float* w_proj   = (const float*)d_in[2];
    const float* ln_g     = (const float*)d_in[3];
    const float* ln_b     = (const float*)d_in[4];
    float* out = (float*)d_out;

    cudaFuncSetAttribute(fused_kernel, cudaFuncAttributeMaxDynamicSharedMemorySize,
                         SMEM_TOT);

    ln_kernel<<<BT_, 256>>>(residual, ln_g, ln_b);
    kvext_kernel<<<4096, 256>>>(w_fc, w_proj);
    fused_kernel<<<dim3(64, QH_, NSPLIT), 256, SMEM_TOT>>>();
    reduce_kernel<<<BT_ * C_ / 1024, 256>>>(residual, out);
}

// round 17
// speedup vs baseline: 1.1027x; 1.0383x over previous
#include <cuda_runtime.h>
#include <cuda_fp16.h>
#include <cstdint>

#define BT_   8192
#define C_    1024
#define S_    4096
#define QH_   4
#define EPS_  1e-5f
#define NSPLIT 4
#define SSEG  1024            // S per split

// ---------------- scratch ----------------
__device__ __half g_q[(size_t)BT_ * 1024];   // 16MB [row][h*256 + d]
__device__ __half g_k[(size_t)S_ * 256];     //  2MB [s][d]
__device__ __half g_vt[256ull * S_];         //  2MB [d][s]
__device__ __half g_part[(size_t)NSPLIT * BT_ * C_]; // 67MB fp16 partials

// ---------------- helpers ----------------
__device__ __forceinline__ uint32_t smem_u32(const void* p) {
    uint32_t a;
    asm("{ .reg .u64 t; cvta.to.shared.u64 t, %1; cvt.u32.u64 %0, t; }" : "=r"(a) : "l"(p));
    return a;
}
#define CPA16(saddr, gptr) \
    asm volatile("cp.async.cg.shared.global [%0], [%1], 16;" :: "r"(saddr), "l"(gptr))
#define CPCOMMIT() asm volatile("cp.async.commit_group;" ::: "memory")
#define CPWAIT(n)  asm volatile("cp.async.wait_group " #n ";" ::: "memory")
#define BARHALF(id) asm volatile("bar.sync %0, 128;" :: "r"(id) : "memory")

__device__ __forceinline__ void ldsm4(uint32_t* r, uint32_t addr) {
    asm volatile("ldmatrix.sync.aligned.m8n8.x4.shared.b16 {%0,%1,%2,%3}, [%4];"
                 : "=r"(r[0]), "=r"(r[1]), "=r"(r[2]), "=r"(r[3]) : "r"(addr));
}
__device__ __forceinline__ void mma16816(float* c, const uint32_t* a, const uint32_t* b) {
    asm volatile("mma.sync.aligned.m16n8k16.row.col.f32.f16.f16.f32 "
                 "{%0,%1,%2,%3}, {%4,%5,%6,%7}, {%8,%9}, {%0,%1,%2,%3};"
                 : "+f"(c[0]), "+f"(c[1]), "+f"(c[2]), "+f"(c[3])
                 : "r"(a[0]), "r"(a[1]), "r"(a[2]), "r"(a[3]), "r"(b[0]), "r"(b[1]));
}
__device__ __forceinline__ uint32_t pack_h2(float f0, float f1) {
    __half2 h = __floats2half2_rn(f0, f1);
    return *reinterpret_cast<uint32_t*>(&h);
}

// ---------------------------------------------------------------------------
// LayerNorm -> g_q (fp16), single-pass mean/var
// ---------------------------------------------------------------------------
__global__ void __launch_bounds__(256) ln_kernel(const float* __restrict__ res,
                                                 const float* __restrict__ gam,
                                                 const float* __restrict__ bet) {
    const int row = blockIdx.x;
    const float* x = res + (size_t)row * C_;
    const int t = threadIdx.x;

    float v[4];
    float s = 0.f, q = 0.f;
#pragma unroll
    for (int i = 0; i < 4; i++) {
        v[i] = x[t + 256 * i];
        s += v[i];
        q += v[i] * v[i];
    }

    __shared__ float red_s[8], red_q[8];
    __shared__ float sh_mu, sh_rs;
#pragma unroll
    for (int o = 16; o; o >>= 1) {
        s += __shfl_xor_sync(0xffffffffu, s, o);
        q += __shfl_xor_sync(0xffffffffu, q, o);
    }
    if ((t & 31) == 0) { red_s[t >> 5] = s; red_q[t >> 5] = q; }
    __syncthreads();
    if (t == 0) {
        float ts = 0.f, tq = 0.f;
#pragma unroll
        for (int i = 0; i < 8; i++) { ts += red_s[i]; tq += red_q[i]; }
        float mu = ts * (1.0f / (float)C_);
        float var = tq * (1.0f / (float)C_) - mu * mu;
        sh_mu = mu;
        sh_rs = rsqrtf(var + EPS_);
    }
    __syncthreads();
    const float mu = sh_mu;
    const float rs = sh_rs;

#pragma unroll
    for (int i = 0; i < 4; i++) {
        int c = t + 256 * i;
        float y = (v[i] - mu) * rs * gam[c] + bet[c];
        g_q[(size_t)row * 1024 + c] = __float2half(y);
    }
}

// K + V^T extraction in one kernel
__global__ void __launch_bounds__(256) kvext_kernel(const float* __restrict__ wfc,
                                                    const float* __restrict__ wproj) {
    int idx = blockIdx.x * 256 + threadIdx.x;
    g_k[idx] = __float2half(wfc[idx]);
    float v = wproj[idx];
    int r = idx >> 10, cc = idx & 1023;
    int d = r & 255;
    int s = cc * 4 + (r >> 8);
    g_vt[(size_t)d * 4096 + s] = __float2half(v);
}

// ---------------------------------------------------------------------------
// Reduce: out = residual + sum of 4 fp16 partials
// ---------------------------------------------------------------------------
__global__ void __launch_bounds__(256) reduce_kernel(const float* __restrict__ res,
                                                     float* __restrict__ out) {
    const size_t i = ((size_t)blockIdx.x * 256 + threadIdx.x) * 4;
    float4 acc = *(const float4*)(res + i);
#pragma unroll
    for (int sp = 0; sp < NSPLIT; sp++) {
        uint2 raw = *(const uint2*)(g_part + (size_t)sp * BT_ * C_ + i);
        __half2 h0 = *reinterpret_cast<__half2*>(&raw.x);
        __half2 h1 = *reinterpret_cast<__half2*>(&raw.y);
        float2 f0 = __half22float2(h0);
        float2 f1 = __half22float2(h1);
        acc.x += f0.x; acc.y += f0.y; acc.z += f1.x; acc.w += f1.y;
    }
    *(float4*)(out + i) = acc;
}

// ---------------------------------------------------------------------------
// Fused kernel: CTA = 128 rows x 1 head x 1 S-split(1024); S chunks of 64.
// Pure fp16; K,V double-buffered. Warp maps chosen so P handoff is
// half-CTA-local: mid barrier = two independent bar.sync(id,128).
// GEMM1: my=wid>>1 (32m), sx=wid&1 (32s). GEMM2: mh=wid>>2 (64m), dq=wid&3 (64d).
// SMEM: Q[128][528B], P[128][144B], K 2x[64][528B], V 2x[256][144B] = 227328B.
// ---------------------------------------------------------------------------
#define SQ_OFF   0            // 128*528    = 67584
#define SP_OFF   67584        // 128*144    = 18432
#define SK_OFF   86016        // 2 x 64*528  = 67584
#define SK_SZ    33792
#define SV_OFF   153600       // 2 x 256*144 = 73728
#define SV_SZ    36864
#define SMEM_TOT 227328
#define NIT      (SSEG / 64)  // 16 chunks per split

__global__ void __launch_bounds__(256, 1) fused_kernel() {
    extern __shared__ char smem[];
    const uint32_t sb = smem_u32(smem);

    const int t = threadIdx.x;
    const int lane = t & 31;
    const int wid = t >> 5;
    const int r = lane >> 2;        // 0..7
    const int u = lane & 3;         // 0..3
    const int head = blockIdx.y;
    const int row0 = blockIdx.x * 128;
    const int sBase = blockIdx.z * SSEG;

    // GEMM1 warp coords: my = m-group (32 rows), sx = s-half (32 cols)
    const int my = wid >> 1;        // 0..3
    const int sx = wid & 1;         // 0..1
    // GEMM2 warp coords: mh = m-half (64 rows), dq = d-quarter (64 cols)
    const int mh = wid >> 2;        // 0..1
    const int dq = wid & 3;         // 0..3
    const int half_id = 1 + (wid >> 2);   // named barrier id per CTA half

    // ---- prologue: issue Q + K(0) + V(0) as one group ----
#pragma unroll
    for (int i = 0; i < 16; i++) {
        int idx = i * 256 + t;
        int m = idx >> 5, c = idx & 31;
        CPA16(sb + SQ_OFF + m * 528 + c * 16,
              (const void*)(g_q + (size_t)(row0 + m) * 1024 + head * 256 + c * 8));
    }
#pragma unroll
    for (int i = 0; i < 8; i++) {
        int idx = i * 256 + t;
        int s = idx >> 5, c = idx & 31;
        CPA16(sb + SK_OFF + s * 528 + c * 16,
              (const void*)(g_k + (size_t)(sBase + s) * 256 + c * 8));
    }
#pragma unroll
    for (int i = 0; i < 8; i++) {
        int idx = i * 256 + t;
        int d = idx >> 3, c = idx & 7;
        CPA16(sb + SV_OFF + d * 144 + c * 16,
              (const void*)(g_vt + (size_t)d * 4096 + sBase + c * 8));
    }
    CPCOMMIT();
    CPWAIT(0);
    __syncthreads();

    // ldmatrix lane addressing
    const uint32_t qa = sb + SQ_OFF + (uint32_t)((my * 32 + (lane & 15)) * 528 + (lane >> 4) * 16);
    const int brow = (lane & 7) + ((lane >> 4) << 3);
    const int bc8  = ((lane >> 3) & 1) << 3;
    const uint32_t kb0 = sb + SK_OFF + (uint32_t)((sx * 32 + brow) * 528 + bc8 * 2);
    const uint32_t pa = sb + SP_OFF + (uint32_t)((mh * 64 + (lane & 15)) * 144 + (lane >> 4) * 16);
    const uint32_t vb0 = sb + SV_OFF + (uint32_t)((dq * 64 + brow) * 144 + bc8 * 2);
    const uint32_t pw = sb + SP_OFF + (uint32_t)((my * 32 + r) * 144 + (sx * 32 + 2 * u) * 2);

    float c2[4][8][4];
#pragma unroll
    for (int a = 0; a < 4; a++)
#pragma unroll
        for (int b = 0; b < 8; b++)
#pragma unroll
            for (int e = 0; e < 4; e++) c2[a][b][e] = 0.f;

    for (int it = 0; it < NIT; it++) {
        const int buf = it & 1;
        const uint32_t kb = kb0 + buf * SK_SZ;
        const uint32_t vb = vb0 + buf * SV_SZ;

        // issue K(it+1) + V(it+1) into the other buffers (fly under both GEMMs)
        if (it < NIT - 1) {
            const int sn = sBase + (it + 1) * 64;
            const uint32_t ko = sb + SK_OFF + (buf ^ 1) * SK_SZ;
            const uint32_t vo = sb + SV_OFF + (buf ^ 1) * SV_SZ;
#pragma unroll
            for (int i = 0; i < 8; i++) {
                int idx = i * 256 + t;
                int s = idx >> 5, c = idx & 31;
                CPA16(ko + s * 528 + c * 16,
                      (const void*)(g_k + (size_t)(sn + s) * 256 + c * 8));
            }
#pragma unroll
            for (int i = 0; i < 8; i++) {
                int idx = i * 256 + t;
                int d = idx >> 3, c = idx & 7;
                CPA16(vo + d * 144 + c * 16,
                      (const void*)(g_vt + (size_t)d * 4096 + sn + c * 8));
            }
            CPCOMMIT();
        }

        // ---- GEMM1: scores[128 x 64] ----
        float c1[2][4][4];
#pragma unroll
        for (int a = 0; a < 2; a++)
#pragma unroll
            for (int b = 0; b < 4; b++)
#pragma unroll
                for (int e = 0; e < 4; e++) c1[a][b][e] = 0.f;

#pragma unroll
        for (int ks = 0; ks < 16; ks++) {
            uint32_t a0[4], a1[4], b0[4], b1[4];
            ldsm4(a0, qa + ks * 32);
            ldsm4(a1, qa + 16 * 528 + ks * 32);
            ldsm4(b0, kb + ks * 32);
            ldsm4(b1, kb + 16 * 528 + ks * 32);
            mma16816(c1[0][0], a0, b0);  mma16816(c1[0][1], a0, b0 + 2);
            mma16816(c1[0][2], a0, b1);  mma16816(c1[0][3], a0, b1 + 2);
            mma16816(c1[1][0], a1, b0);  mma16816(c1[1][1], a1, b0 + 2);
            mma16816(c1[1][2], a1, b1);  mma16816(c1[1][3], a1, b1 + 2);
        }

        // ---- relu^2 -> P (fp16) smem ----
#pragma unroll
        for (int mt = 0; mt < 2; mt++) {
#pragma unroll
            for (int nt = 0; nt < 4; nt++) {
                uint32_t base = pw + (uint32_t)(mt * 16 * 144 + nt * 16);
#pragma unroll
                for (int half = 0; half < 2; half++) {
                    float p0 = fmaxf(c1[mt][nt][half * 2], 0.f);
                    float p1 = fmaxf(c1[mt][nt][half * 2 + 1], 0.f);
                    uint32_t a = base + half * (8 * 144);
                    *(uint32_t*)(smem + (a - sb)) = pack_h2(p0 * p0, p1 * p1);
                }
            }
        }
        BARHALF(half_id);       // mid handoff: P half written by/read by same 4 warps

        // ---- GEMM2: O[128 x 256] += P . V^T ----
#pragma unroll
        for (int ks = 0; ks < 4; ks++) {
            uint32_t Ph[4][4];
#pragma unroll
            for (int mt = 0; mt < 4; mt++)
                ldsm4(Ph[mt], pa + (uint32_t)(mt * 16 * 144 + ks * 32));
#pragma unroll
            for (int h = 0; h < 4; h++) {
                uint32_t vh[4];
                ldsm4(vh, vb + (uint32_t)(h * 16 * 144 + ks * 32));
#pragma unroll
                for (int mt = 0; mt < 4; mt++) {
                    mma16816(c2[mt][2 * h],     Ph[mt], vh);
                    mma16816(c2[mt][2 * h + 1], Ph[mt], vh + 2);
                }
            }
        }

        if (it < NIT - 1) CPWAIT(0);   // K(it+1)+V(it+1) landed
        __syncthreads();               // full barrier: buffer flip + P reuse
    }

    // ---- epilogue: write partial O as fp16 (no residual) ----
    __half* po = g_part + (size_t)blockIdx.z * BT_ * C_;
#pragma unroll
    for (int mt = 0; mt < 4; mt++) {
        const int rowA = row0 + mh * 64 + mt * 16 + r;
        const int rowB = rowA + 8;
        __half* oA = po + (size_t)rowA * C_ + head * 256;
        __half* oB = po + (size_t)rowB * C_ + head * 256;
#pragma unroll
        for (int j = 0; j < 8; j++) {
            const int col = dq * 64 + (j >> 1) * 16 + (j & 1) * 8 + 2 * u;
            *(uint32_t*)(oA + col) = pack_h2(c2[mt][j][0], c2[mt][j][1]);
            *(uint32_t*)(oB + col) = pack_h2(c2[mt][j][2], c2[mt][j][3]);
        }
    }
}

// ---------------------------------------------------------------------------
extern "C" void kernel_launch(void* const* d_in, const int* in_sizes, int n_in,
                              void* d_out, int out_size) {
    (void)in_sizes; (void)n_in; (void)out_size;
    const float* residual = (const float*)d_in[0];
    const float* w_fc     = (const float*)d_in[1];
    const float* w_proj   = (const float*)d_in[2];
    const float* ln_g     = (const float*)d_in[3];
    const float* ln_b     = (const float*)d_in[4];
    float* out = (float*)d_out;

    cudaFuncSetAttribute(fused_kernel, cudaFuncAttributeMaxDynamicSharedMemorySize,
                         SMEM_TOT);

    ln_kernel<<<BT_, 256>>>(residual, ln_g, ln_b);
    kvext_kernel<<<4096, 256>>>(w_fc, w_proj);
    fused_kernel<<<dim3(64, QH_, NSPLIT), 256, SMEM_TOT>>>();
    reduce_kernel<<<BT_ * C_ / 1024, 256>>>(residual, out);
}